// round 1
// baseline (speedup 1.0000x reference)
#include <cuda_runtime.h>
#include <math.h>

#define B_ROWS 16384
#define D_DIM  2048
#define H_DIM  512
#define NCHUNK 8      // H_DIM / BN
#define BM 128
#define BN 64
#define BK 16

// ---------------- scratch (no allocations allowed) ----------------
__device__ float g_partial[B_ROWS * NCHUNK];  // per-row per-colchunk partial logits
__device__ int   g_k[B_ROWS];                 // per-row k (rank of threshold)
__device__ float g_l1row[B_ROWS];             // per-row sum |sparse_x|

// ---------------- stage 1: fused predictor GEMM -------------------
// Computes, for block (bx=col chunk of 64, by=row tile of 128):
//   h[b, j] = x[b,:] @ W1[:, j] + b1[j]   (fp32)
// then relu and reduces with W2[j] into g_partial[b*8 + bx].
__global__ void __launch_bounds__(256) predictor_gemm(
    const float* __restrict__ x, const float* __restrict__ W1,
    const float* __restrict__ b1, const float* __restrict__ W2)
{
    __shared__ float As[BK][BM];   // transposed x tile
    __shared__ float Bs[BK][BN];   // W1 tile
    __shared__ float red[16][BM];  // logit-partial reduction

    const int tid = threadIdx.x;
    const int bx = blockIdx.x;          // col chunk (0..7)
    const int by = blockIdx.y;          // row tile (0..127)
    const int m0 = by * BM;
    const int n0 = bx * BN;
    const int ty = tid >> 4;            // 0..15 -> 8 rows each
    const int tx = tid & 15;            // 0..15 -> 4 cols each

    float acc[8][4];
#pragma unroll
    for (int i = 0; i < 8; i++)
#pragma unroll
        for (int j = 0; j < 4; j++) acc[i][j] = 0.f;

    for (int kt = 0; kt < D_DIM; kt += BK) {
        // load A tile (128 rows x 16 k), store transposed
#pragma unroll
        for (int p = 0; p < 2; p++) {
            int idx = tid + p * 256;
            int row = idx >> 2;
            int c4  = (idx & 3) * 4;
            float4 v = *reinterpret_cast<const float4*>(
                &x[(size_t)(m0 + row) * D_DIM + kt + c4]);
            As[c4 + 0][row] = v.x;
            As[c4 + 1][row] = v.y;
            As[c4 + 2][row] = v.z;
            As[c4 + 3][row] = v.w;
        }
        // load B tile (16 k x 64 n)
        {
            int kr = tid >> 4;
            int n4 = (tid & 15) * 4;
            float4 v = *reinterpret_cast<const float4*>(
                &W1[(size_t)(kt + kr) * H_DIM + n0 + n4]);
            *reinterpret_cast<float4*>(&Bs[kr][n4]) = v;
        }
        __syncthreads();

#pragma unroll
        for (int kk = 0; kk < BK; kk++) {
            float a[8], b[4];
            float4 a0 = *reinterpret_cast<float4*>(&As[kk][ty * 8]);
            float4 a1 = *reinterpret_cast<float4*>(&As[kk][ty * 8 + 4]);
            a[0]=a0.x; a[1]=a0.y; a[2]=a0.z; a[3]=a0.w;
            a[4]=a1.x; a[5]=a1.y; a[6]=a1.z; a[7]=a1.w;
            float4 bv = *reinterpret_cast<float4*>(&Bs[kk][tx * 4]);
            b[0]=bv.x; b[1]=bv.y; b[2]=bv.z; b[3]=bv.w;
#pragma unroll
            for (int i = 0; i < 8; i++)
#pragma unroll
                for (int j = 0; j < 4; j++)
                    acc[i][j] = fmaf(a[i], b[j], acc[i][j]);
        }
        __syncthreads();
    }

    // epilogue: bias, relu, weight by W2, reduce across the 4 local cols
    float bb1[4], ww2[4];
#pragma unroll
    for (int j = 0; j < 4; j++) {
        bb1[j] = b1[n0 + tx * 4 + j];
        ww2[j] = W2[n0 + tx * 4 + j];
    }
#pragma unroll
    for (int i = 0; i < 8; i++) {
        float s = 0.f;
#pragma unroll
        for (int j = 0; j < 4; j++) {
            float h = acc[i][j] + bb1[j];
            h = fmaxf(h, 0.f);
            s = fmaf(h, ww2[j], s);
        }
        red[tx][ty * 8 + i] = s;
    }
    __syncthreads();
    // reduce over the 16 tx groups per row (fixed order -> deterministic)
    if (tid < BM) {
        float s = 0.f;
#pragma unroll
        for (int t = 0; t < 16; t++) s += red[t][tid];
        g_partial[(size_t)(m0 + tid) * NCHUNK + bx] = s;
    }
}

// ---------------- stage 2: logits -> sparsity, k -------------------
__global__ void sparsity_kernel(const float* __restrict__ b2,
                                float* __restrict__ out_sp)
{
    int b = blockIdx.x * 256 + threadIdx.x;
    if (b >= B_ROWS) return;
    float s = b2[0];
#pragma unroll
    for (int c = 0; c < NCHUNK; c++) s += g_partial[(size_t)b * NCHUNK + c];
    float sig = 1.f / (1.f + expf(-s));
    float sp  = 0.05f + 0.25f * sig;
    out_sp[b] = sp;
    // jnp.round = round half-even = rintf (default rounding mode)
    int k = (int)rintf((float)D_DIM * (1.f - sp));
    g_k[b] = (k < 1) ? 1 : k;
}

// ---------------- stage 3: exact per-row radix select + mask -------
__global__ void __launch_bounds__(256) select_mask_kernel(
    const float* __restrict__ x,
    float* __restrict__ out_sparse, float* __restrict__ out_mask,
    float* __restrict__ out_act)
{
    __shared__ float        xs[D_DIM];
    __shared__ unsigned int hist[256];
    __shared__ unsigned int scan[256];
    __shared__ float        fred[256];
    __shared__ unsigned int s_prefix, s_kk;

    const int row = blockIdx.x;
    const int tid = threadIdx.x;
    const float* xr = x + (size_t)row * D_DIM;

#pragma unroll
    for (int p = 0; p < 2; p++) {
        int i4 = (tid + p * 256) * 4;
        *reinterpret_cast<float4*>(&xs[i4]) =
            *reinterpret_cast<const float4*>(&xr[i4]);
    }
    if (tid == 0) { s_prefix = 0u; s_kk = (unsigned int)g_k[row]; }
    __syncthreads();

    // MSD radix select: find the s_kk-th smallest |x| bit pattern exactly.
    for (int shift = 24; shift >= 0; shift -= 8) {
        hist[tid] = 0u;
        __syncthreads();
        unsigned int prefix = s_prefix;
        unsigned int kcur   = s_kk;
        unsigned int himask = (shift == 24) ? 0u : (0xFFFFFFFFu << (shift + 8));
        for (int i = tid; i < D_DIM; i += 256) {
            unsigned int key = __float_as_uint(fabsf(xs[i]));
            if ((key & himask) == prefix)
                atomicAdd(&hist[(key >> shift) & 255u], 1u);
        }
        __syncthreads();
        // inclusive prefix sum over 256 bins (Hillis-Steele)
        scan[tid] = hist[tid];
        __syncthreads();
        for (int off = 1; off < 256; off <<= 1) {
            unsigned int t = (tid >= off) ? scan[tid - off] : 0u;
            __syncthreads();
            scan[tid] += t;
            __syncthreads();
        }
        unsigned int cum  = scan[tid];
        unsigned int prev = tid ? scan[tid - 1] : 0u;
        if (cum >= kcur && prev < kcur) {
            s_prefix = prefix | ((unsigned int)tid << shift);
            s_kk     = kcur - prev;
        }
        __syncthreads();
    }

    const float thr = __uint_as_float(s_prefix);

    // mask + sparse write (coalesced), local counts
    int   cnt = 0;
    float l1  = 0.f;
    for (int i = tid; i < D_DIM; i += 256) {
        float v = xs[i];
        float a = fabsf(v);
        bool  m = (a > thr);
        out_mask  [(size_t)row * D_DIM + i] = m ? 1.f : 0.f;
        out_sparse[(size_t)row * D_DIM + i] = m ? v : 0.f;
        if (m) { cnt++; l1 += a; }
    }
    // deterministic block reduction
    scan[tid] = (unsigned int)cnt;
    fred[tid] = l1;
    __syncthreads();
    for (int off = 128; off > 0; off >>= 1) {
        if (tid < off) {
            scan[tid] += scan[tid + off];
            fred[tid] += fred[tid + off];
        }
        __syncthreads();
    }
    if (tid == 0) {
        out_act[row]  = (float)scan[0] / (float)D_DIM;
        g_l1row[row]  = fred[0];
    }
}

// ---------------- stage 4: deterministic l1 mean -------------------
__global__ void l1_reduce(float* __restrict__ out_l1)
{
    __shared__ float sm[256];
    const int tid = threadIdx.x;
    float s = 0.f;
    for (int i = tid; i < B_ROWS; i += 256) s += g_l1row[i];
    sm[tid] = s;
    __syncthreads();
    for (int off = 128; off > 0; off >>= 1) {
        if (tid < off) sm[tid] += sm[tid + off];
        __syncthreads();
    }
    if (tid == 0) out_l1[0] = sm[0] / (float)B_ROWS;
}

// ---------------- launch ------------------------------------------
extern "C" void kernel_launch(void* const* d_in, const int* in_sizes, int n_in,
                              void* d_out, int out_size)
{
    const float* x  = (const float*)d_in[0];
    const float* W1 = (const float*)d_in[1];
    const float* b1 = (const float*)d_in[2];
    const float* W2 = (const float*)d_in[3];
    const float* b2 = (const float*)d_in[4];

    float* out        = (float*)d_out;
    float* out_sparse = out;                                   // [B, D]
    float* out_mask   = out + (size_t)B_ROWS * D_DIM;          // [B, D]
    float* out_sp     = out + 2 * (size_t)B_ROWS * D_DIM;      // [B, 1]
    float* out_act    = out_sp + B_ROWS;                       // [B]
    float* out_l1     = out_act + B_ROWS;                      // [1]

    dim3 g1(NCHUNK, B_ROWS / BM);      // 8 x 128 blocks
    predictor_gemm<<<g1, 256>>>(x, W1, b1, W2);
    sparsity_kernel<<<B_ROWS / 256, 256>>>(b2, out_sp);
    select_mask_kernel<<<B_ROWS, 256>>>(x, out_sparse, out_mask, out_act);
    l1_reduce<<<1, 256>>>(out_l1);
}

// round 4
// speedup vs baseline: 1.8035x; 1.8035x over previous
#include <cuda_runtime.h>
#include <cuda_fp16.h>
#include <math.h>
#include <stdint.h>

#define B_ROWS 16384
#define D_DIM  2048
#define H_DIM  512
#define NCHUNK 4          // 512 / BN

// ------------------------- device scratch -------------------------
__device__ __half g_xs[2ull * B_ROWS * D_DIM];   // x split hi/lo (fp16)
__device__ __half g_ws[2ull * H_DIM * D_DIM];    // W1^T split hi/lo, [H, D]
__device__ float  g_partial[B_ROWS * NCHUNK];
__device__ int    g_k[B_ROWS];
__device__ float  g_l1row[B_ROWS];

// ------------------------- helpers --------------------------------
__device__ __forceinline__ uint32_t smem_u32(const void* p) {
    uint32_t a;
    asm("{ .reg .u64 t; cvta.to.shared.u64 t, %1; cvt.u32.u64 %0, t; }" : "=r"(a) : "l"(p));
    return a;
}
__device__ __forceinline__ uint32_t swz128(uint32_t b) { return b ^ ((b >> 3) & 0x70u); }

__device__ __forceinline__ void cp16(uint32_t dst, const void* src) {
    asm volatile("cp.async.cg.shared.global [%0], [%1], 16;" :: "r"(dst), "l"(src) : "memory");
}
__device__ __forceinline__ void cp_commit() {
    asm volatile("cp.async.commit_group;" ::: "memory");
}
template <int N>
__device__ __forceinline__ void cp_wait() {
    asm volatile("cp.async.wait_group %0;" :: "n"(N) : "memory");
}
__device__ __forceinline__ void ldsm4(uint32_t* r, uint32_t addr) {
    asm volatile("ldmatrix.sync.aligned.m8n8.x4.shared.b16 {%0,%1,%2,%3}, [%4];"
                 : "=r"(r[0]), "=r"(r[1]), "=r"(r[2]), "=r"(r[3]) : "r"(addr));
}
__device__ __forceinline__ void mma16816(float* c, const uint32_t* a,
                                         uint32_t b0, uint32_t b1) {
    asm volatile(
        "mma.sync.aligned.m16n8k16.row.col.f32.f16.f16.f32 "
        "{%0,%1,%2,%3}, {%4,%5,%6,%7}, {%8,%9}, {%0,%1,%2,%3};"
        : "+f"(c[0]), "+f"(c[1]), "+f"(c[2]), "+f"(c[3])
        : "r"(a[0]), "r"(a[1]), "r"(a[2]), "r"(a[3]), "r"(b0), "r"(b1));
}

__device__ __forceinline__ void split2(float f, __half& h, __half& l) {
    h = __float2half_rn(f);
    l = __float2half_rn(f - __half2float(h));
}

// --------------- stage 0a: split x into 2 fp16 planes --------------
__global__ void __launch_bounds__(256) convert_x(const float* __restrict__ x)
{
    size_t i4 = ((size_t)blockIdx.x * 256 + threadIdx.x) * 4;
    if (i4 >= (size_t)B_ROWS * D_DIM) return;
    float4 v = *reinterpret_cast<const float4*>(x + i4);
    __half h[4], l[4];
    split2(v.x, h[0], l[0]);
    split2(v.y, h[1], l[1]);
    split2(v.z, h[2], l[2]);
    split2(v.w, h[3], l[3]);
    const size_t P = (size_t)B_ROWS * D_DIM;
    *reinterpret_cast<uint2*>(&g_xs[i4])     = *reinterpret_cast<uint2*>(h);
    *reinterpret_cast<uint2*>(&g_xs[P + i4]) = *reinterpret_cast<uint2*>(l);
}

// --------------- stage 0b: split + transpose W1 --------------------
__global__ void __launch_bounds__(256) convert_w1(const float* __restrict__ W1)
{
    size_t idx = (size_t)blockIdx.x * 256 + threadIdx.x;   // over [D, H]
    if (idx >= (size_t)D_DIM * H_DIM) return;
    int k = (int)(idx / H_DIM);
    int n = (int)(idx % H_DIM);
    __half h, l;
    split2(W1[idx], h, l);
    const size_t P = (size_t)H_DIM * D_DIM;
    size_t o = (size_t)n * D_DIM + k;
    g_ws[o]     = h;
    g_ws[P + o] = l;
}

// --------------- stage 1: HMMA split-2 GEMM + fused epilogue -------
// CTA tile: 128(M) x 128(N), BK=64. Grid (4 n-tiles, 128 m-tiles).
// smem: 2 stages x 2 planes x (A 16KB + B 16KB) = 128KB (+1KB align).
#define SM_DYN (131072 + 1024)

__global__ void __launch_bounds__(256, 1) gemm_predictor(
    const float* __restrict__ b1, const float* __restrict__ W2)
{
    extern __shared__ char smem_raw[];
    __shared__ float red[128][4];

    const uint32_t sb = (smem_u32(smem_raw) + 1023u) & ~1023u;
    const int tid  = threadIdx.x;
    const int lane = tid & 31;
    const int w    = tid >> 5;
    const int wm   = w >> 2;          // 0..1  (M warp row)
    const int wn   = w & 3;           // 0..3  (N warp col)
    const int m0   = blockIdx.y * 128;
    const int n0   = blockIdx.x * 128;
    const size_t PX = (size_t)B_ROWS * D_DIM;
    const size_t PW = (size_t)H_DIM * D_DIM;

    float c[4][4][4];
#pragma unroll
    for (int i = 0; i < 4; i++)
#pragma unroll
        for (int j = 0; j < 4; j++)
#pragma unroll
            for (int e = 0; e < 4; e++) c[i][j][e] = 0.f;

    auto load_tiles = [&](int stage, int kt) {
        const int k0 = kt * 64;
#pragma unroll
        for (int p = 0; p < 2; ++p) {
            const __half* asrc = g_xs + (size_t)p * PX;
            const __half* bsrc = g_ws + (size_t)p * PW;
            const uint32_t abase = sb + (uint32_t)(stage * 2 + p) * 16384u;
            const uint32_t bbase = sb + 65536u + (uint32_t)(stage * 2 + p) * 16384u;
#pragma unroll
            for (int i = 0; i < 4; ++i) {
                int u = tid + i * 256;            // 0..1023
                int row = u >> 3, cc = u & 7;
                uint32_t soff = swz128((uint32_t)(row * 128 + cc * 16));
                cp16(abase + soff, asrc + (size_t)(m0 + row) * D_DIM + k0 + cc * 8);
                cp16(bbase + soff, bsrc + (size_t)(n0 + row) * D_DIM + k0 + cc * 8);
            }
        }
    };

    auto compute = [&](int stage) {
        const uint32_t A0 = sb + (uint32_t)(stage * 2 + 0) * 16384u;
        const uint32_t A1 = sb + (uint32_t)(stage * 2 + 1) * 16384u;
        const uint32_t B0 = sb + 65536u + (uint32_t)(stage * 2 + 0) * 16384u;
        const uint32_t B1 = sb + 65536u + (uint32_t)(stage * 2 + 1) * 16384u;
#pragma unroll
        for (int s = 0; s < 4; ++s) {
            const int chunk = (s * 2 + (lane >> 4)) * 16;
            uint32_t a[2][4][4];
#pragma unroll
            for (int mt = 0; mt < 4; ++mt) {
                int row = wm * 64 + mt * 16 + (lane & 15);
                uint32_t off = swz128((uint32_t)(row * 128 + chunk));
                ldsm4(a[0][mt], A0 + off);
                ldsm4(a[1][mt], A1 + off);
            }
            uint32_t br[2][2][4];
#pragma unroll
            for (int np = 0; np < 2; ++np) {
                int row = wn * 32 + np * 16 + (lane & 15);
                uint32_t off = swz128((uint32_t)(row * 128 + chunk));
                ldsm4(br[0][np], B0 + off);
                ldsm4(br[1][np], B1 + off);
            }
#pragma unroll
            for (int mt = 0; mt < 4; ++mt)
#pragma unroll
                for (int nt = 0; nt < 4; ++nt) {
                    const int np = nt >> 1, hb = nt & 1;
                    const uint32_t bh0 = br[0][np][hb], bh1 = br[0][np][hb + 2];
                    const uint32_t bl0 = br[1][np][hb], bl1 = br[1][np][hb + 2];
                    mma16816(c[mt][nt], a[0][mt], bh0, bh1);   // hh
                    mma16816(c[mt][nt], a[0][mt], bl0, bl1);   // hl
                    mma16816(c[mt][nt], a[1][mt], bh0, bh1);   // lh
                }
        }
    };

    load_tiles(0, 0);
    cp_commit();
    for (int kt = 0; kt < 32; ++kt) {
        if (kt + 1 < 32) {
            load_tiles((kt + 1) & 1, kt + 1);
            cp_commit();
            cp_wait<1>();
        } else {
            cp_wait<0>();
        }
        __syncthreads();
        compute(kt & 1);
        __syncthreads();
    }

    // epilogue: relu(c + b1) dot W2 over this CTA's 128 cols -> partial
#pragma unroll
    for (int mt = 0; mt < 4; ++mt) {
#pragma unroll
        for (int h = 0; h < 2; ++h) {
            float p = 0.f;
#pragma unroll
            for (int nt = 0; nt < 4; ++nt)
#pragma unroll
                for (int e = 0; e < 2; ++e) {
                    int col = n0 + wn * 32 + nt * 8 + (lane & 3) * 2 + e;
                    float v = c[mt][nt][h * 2 + e] + b1[col];
                    v = fmaxf(v, 0.f);
                    p = fmaf(v, W2[col], p);
                }
            p += __shfl_xor_sync(0xffffffffu, p, 1);
            p += __shfl_xor_sync(0xffffffffu, p, 2);
            if ((lane & 3) == 0) {
                int row = wm * 64 + mt * 16 + (lane >> 2) + 8 * h;
                red[row][wn] = p;
            }
        }
    }
    __syncthreads();
    if (tid < 128) {
        float s = red[tid][0] + red[tid][1] + red[tid][2] + red[tid][3];
        g_partial[(size_t)(m0 + tid) * NCHUNK + blockIdx.x] = s;
    }
}

// ---------------- stage 2: logits -> sparsity, k -------------------
__global__ void sparsity_kernel(const float* __restrict__ b2,
                                float* __restrict__ out_sp)
{
    int b = blockIdx.x * 256 + threadIdx.x;
    if (b >= B_ROWS) return;
    float s = b2[0];
#pragma unroll
    for (int cc = 0; cc < NCHUNK; cc++) s += g_partial[(size_t)b * NCHUNK + cc];
    float sig = 1.f / (1.f + expf(-s));
    float sp  = 0.05f + 0.25f * sig;
    out_sp[b] = sp;
    int k = (int)rintf((float)D_DIM * (1.f - sp));   // round half-even
    g_k[b] = (k < 1) ? 1 : k;
}

// ---------------- stage 3: exact per-row radix select + mask -------
__global__ void __launch_bounds__(256) select_mask_kernel(
    const float* __restrict__ x,
    float* __restrict__ out_sparse, float* __restrict__ out_mask,
    float* __restrict__ out_act)
{
    __shared__ float        xs[D_DIM];
    __shared__ unsigned int hist[256];
    __shared__ unsigned int scan[256];
    __shared__ float        fred[256];
    __shared__ unsigned int s_prefix, s_kk;

    const int row = blockIdx.x;
    const int tid = threadIdx.x;
    const float* xr = x + (size_t)row * D_DIM;

#pragma unroll
    for (int p = 0; p < 2; p++) {
        int i4 = (tid + p * 256) * 4;
        *reinterpret_cast<float4*>(&xs[i4]) =
            *reinterpret_cast<const float4*>(&xr[i4]);
    }
    if (tid == 0) { s_prefix = 0u; s_kk = (unsigned int)g_k[row]; }
    __syncthreads();

    for (int shift = 24; shift >= 0; shift -= 8) {
        hist[tid] = 0u;
        __syncthreads();
        unsigned int prefix = s_prefix;
        unsigned int kcur   = s_kk;
        unsigned int himask = (shift == 24) ? 0u : (0xFFFFFFFFu << (shift + 8));
        for (int i = tid; i < D_DIM; i += 256) {
            unsigned int key = __float_as_uint(fabsf(xs[i]));
            if ((key & himask) == prefix)
                atomicAdd(&hist[(key >> shift) & 255u], 1u);
        }
        __syncthreads();
        scan[tid] = hist[tid];
        __syncthreads();
        for (int off = 1; off < 256; off <<= 1) {
            unsigned int t = (tid >= off) ? scan[tid - off] : 0u;
            __syncthreads();
            scan[tid] += t;
            __syncthreads();
        }
        unsigned int cum  = scan[tid];
        unsigned int prev = tid ? scan[tid - 1] : 0u;
        if (cum >= kcur && prev < kcur) {
            s_prefix = prefix | ((unsigned int)tid << shift);
            s_kk     = kcur - prev;
        }
        __syncthreads();
    }

    const float thr = __uint_as_float(s_prefix);

    int   cnt = 0;
    float l1  = 0.f;
    for (int i = tid; i < D_DIM; i += 256) {
        float v = xs[i];
        float a = fabsf(v);
        bool  m = (a > thr);
        out_mask  [(size_t)row * D_DIM + i] = m ? 1.f : 0.f;
        out_sparse[(size_t)row * D_DIM + i] = m ? v : 0.f;
        if (m) { cnt++; l1 += a; }
    }
    scan[tid] = (unsigned int)cnt;
    fred[tid] = l1;
    __syncthreads();
    for (int off = 128; off > 0; off >>= 1) {
        if (tid < off) {
            scan[tid] += scan[tid + off];
            fred[tid] += fred[tid + off];
        }
        __syncthreads();
    }
    if (tid == 0) {
        out_act[row] = (float)scan[0] / (float)D_DIM;
        g_l1row[row] = fred[0];
    }
}

// ---------------- stage 4: deterministic l1 mean -------------------
__global__ void l1_reduce(float* __restrict__ out_l1)
{
    __shared__ float sm[256];
    const int tid = threadIdx.x;
    float s = 0.f;
    for (int i = tid; i < B_ROWS; i += 256) s += g_l1row[i];
    sm[tid] = s;
    __syncthreads();
    for (int off = 128; off > 0; off >>= 1) {
        if (tid < off) sm[tid] += sm[tid + off];
        __syncthreads();
    }
    if (tid == 0) out_l1[0] = sm[0] / (float)B_ROWS;
}

// ---------------- launch ------------------------------------------
extern "C" void kernel_launch(void* const* d_in, const int* in_sizes, int n_in,
                              void* d_out, int out_size)
{
    const float* x  = (const float*)d_in[0];
    const float* W1 = (const float*)d_in[1];
    const float* b1 = (const float*)d_in[2];
    const float* W2 = (const float*)d_in[3];
    const float* b2 = (const float*)d_in[4];

    float* out        = (float*)d_out;
    float* out_sparse = out;                                   // [B, D]
    float* out_mask   = out + (size_t)B_ROWS * D_DIM;          // [B, D]
    float* out_sp     = out + 2 * (size_t)B_ROWS * D_DIM;      // [B, 1]
    float* out_act    = out_sp + B_ROWS;                       // [B]
    float* out_l1     = out_act + B_ROWS;                      // [1]

    cudaFuncSetAttribute(gemm_predictor,
                         cudaFuncAttributeMaxDynamicSharedMemorySize, SM_DYN);

    convert_x<<<(B_ROWS * (size_t)D_DIM) / (4 * 256), 256>>>(x);
    convert_w1<<<((size_t)D_DIM * H_DIM) / 256, 256>>>(W1);
    gemm_predictor<<<dim3(4, 128), 256, SM_DYN>>>(b1, W2);
    sparsity_kernel<<<B_ROWS / 256, 256>>>(b2, out_sp);
    select_mask_kernel<<<B_ROWS, 256>>>(x, out_sparse, out_mask, out_act);
    l1_reduce<<<1, 256>>>(out_l1);
}

// round 5
// speedup vs baseline: 1.9632x; 1.0886x over previous
#include <cuda_runtime.h>
#include <cuda_fp16.h>
#include <math.h>
#include <stdint.h>

#define B_ROWS 16384
#define D_DIM  2048
#define H_DIM  512
#define NCHUNK 4          // 512 / 128
#define LO_SCALE   2048.0f          // 2^11
#define LO_INV     4.8828125e-4f    // 2^-11

// ------------------------- device scratch -------------------------
__device__ __half g_xs[2ull * B_ROWS * D_DIM];   // x split hi / scaled-lo
__device__ __half g_ws[2ull * H_DIM * D_DIM];    // W1^T split hi / scaled-lo [H,D]
__device__ float  g_partial[B_ROWS * NCHUNK];
__device__ int    g_k[B_ROWS];
__device__ float  g_l1row[B_ROWS];

// ------------------------- helpers --------------------------------
__device__ __forceinline__ uint32_t smem_u32(const void* p) {
    uint32_t a;
    asm("{ .reg .u64 t; cvta.to.shared.u64 t, %1; cvt.u32.u64 %0, t; }" : "=r"(a) : "l"(p));
    return a;
}
__device__ __forceinline__ uint32_t swz128(uint32_t b) { return b ^ ((b >> 3) & 0x70u); }

__device__ __forceinline__ void cp16(uint32_t dst, const void* src) {
    asm volatile("cp.async.cg.shared.global [%0], [%1], 16;" :: "r"(dst), "l"(src) : "memory");
}
__device__ __forceinline__ void cp_commit() {
    asm volatile("cp.async.commit_group;" ::: "memory");
}
template <int N>
__device__ __forceinline__ void cp_wait() {
    asm volatile("cp.async.wait_group %0;" :: "n"(N) : "memory");
}
__device__ __forceinline__ void ldsm4(uint32_t* r, uint32_t addr) {
    asm volatile("ldmatrix.sync.aligned.m8n8.x4.shared.b16 {%0,%1,%2,%3}, [%4];"
                 : "=r"(r[0]), "=r"(r[1]), "=r"(r[2]), "=r"(r[3]) : "r"(addr));
}
__device__ __forceinline__ void mma16816(float* c, const uint32_t* a,
                                         uint32_t b0, uint32_t b1) {
    asm volatile(
        "mma.sync.aligned.m16n8k16.row.col.f32.f16.f16.f32 "
        "{%0,%1,%2,%3}, {%4,%5,%6,%7}, {%8,%9}, {%0,%1,%2,%3};"
        : "+f"(c[0]), "+f"(c[1]), "+f"(c[2]), "+f"(c[3])
        : "r"(a[0]), "r"(a[1]), "r"(a[2]), "r"(a[3]), "r"(b0), "r"(b1));
}

__device__ __forceinline__ void split2s(float f, __half& h, __half& l) {
    h = __float2half_rn(f);
    l = __float2half_rn((f - __half2float(h)) * LO_SCALE);   // scaled: stays normal
}

// --------------- stage 0a: split x into hi / scaled-lo -------------
__global__ void __launch_bounds__(256) convert_x(const float* __restrict__ x)
{
    size_t i4 = ((size_t)blockIdx.x * 256 + threadIdx.x) * 4;
    if (i4 >= (size_t)B_ROWS * D_DIM) return;
    float4 v = *reinterpret_cast<const float4*>(x + i4);
    __half h[4], l[4];
    split2s(v.x, h[0], l[0]);
    split2s(v.y, h[1], l[1]);
    split2s(v.z, h[2], l[2]);
    split2s(v.w, h[3], l[3]);
    const size_t P = (size_t)B_ROWS * D_DIM;
    *reinterpret_cast<uint2*>(&g_xs[i4])     = *reinterpret_cast<uint2*>(h);
    *reinterpret_cast<uint2*>(&g_xs[P + i4]) = *reinterpret_cast<uint2*>(l);
}

// --------------- stage 0b: split + transpose W1 --------------------
__global__ void __launch_bounds__(256) convert_w1(const float* __restrict__ W1)
{
    size_t idx = (size_t)blockIdx.x * 256 + threadIdx.x;   // over [D, H]
    if (idx >= (size_t)D_DIM * H_DIM) return;
    int k = (int)(idx / H_DIM);
    int n = (int)(idx % H_DIM);
    __half h, l;
    split2s(W1[idx], h, l);
    const size_t P = (size_t)H_DIM * D_DIM;
    size_t o = (size_t)n * D_DIM + k;
    g_ws[o]     = h;
    g_ws[P + o] = l;
}

// --------------- stage 1: HMMA split-2 GEMM + fused epilogue -------
// CTA tile: 128(M) x 128(N), BK=64. Grid (4 n-tiles, 128 m-tiles).
#define SM_DYN (131072 + 1024)

__global__ void __launch_bounds__(256, 1) gemm_predictor(
    const float* __restrict__ b1, const float* __restrict__ W2)
{
    extern __shared__ char smem_raw[];
    __shared__ float red[128][4];

    const uint32_t sb = (smem_u32(smem_raw) + 1023u) & ~1023u;
    const int tid  = threadIdx.x;
    const int lane = tid & 31;
    const int w    = tid >> 5;
    const int wm   = w >> 2;          // 0..1
    const int wn   = w & 3;           // 0..3
    const int m0   = blockIdx.y * 128;
    const int n0   = blockIdx.x * 128;
    const size_t PX = (size_t)B_ROWS * D_DIM;
    const size_t PW = (size_t)H_DIM * D_DIM;

    float chi[4][4][4];   // hh products
    float clo[4][4][4];   // hl + lh products (scaled by 2^11)
#pragma unroll
    for (int i = 0; i < 4; i++)
#pragma unroll
        for (int j = 0; j < 4; j++)
#pragma unroll
            for (int e = 0; e < 4; e++) { chi[i][j][e] = 0.f; clo[i][j][e] = 0.f; }

    auto load_tiles = [&](int stage, int kt) {
        const int k0 = kt * 64;
#pragma unroll
        for (int p = 0; p < 2; ++p) {
            const __half* asrc = g_xs + (size_t)p * PX;
            const __half* bsrc = g_ws + (size_t)p * PW;
            const uint32_t abase = sb + (uint32_t)(stage * 2 + p) * 16384u;
            const uint32_t bbase = sb + 65536u + (uint32_t)(stage * 2 + p) * 16384u;
#pragma unroll
            for (int i = 0; i < 4; ++i) {
                int u = tid + i * 256;
                int row = u >> 3, cc = u & 7;
                uint32_t soff = swz128((uint32_t)(row * 128 + cc * 16));
                cp16(abase + soff, asrc + (size_t)(m0 + row) * D_DIM + k0 + cc * 8);
                cp16(bbase + soff, bsrc + (size_t)(n0 + row) * D_DIM + k0 + cc * 8);
            }
        }
    };

    auto compute = [&](int stage) {
        const uint32_t A0 = sb + (uint32_t)(stage * 2 + 0) * 16384u;
        const uint32_t A1 = sb + (uint32_t)(stage * 2 + 1) * 16384u;
        const uint32_t B0 = sb + 65536u + (uint32_t)(stage * 2 + 0) * 16384u;
        const uint32_t B1 = sb + 65536u + (uint32_t)(stage * 2 + 1) * 16384u;
#pragma unroll
        for (int s = 0; s < 4; ++s) {
            const int chunk = (s * 2 + (lane >> 4)) * 16;
            uint32_t br[2][2][4];
#pragma unroll
            for (int np = 0; np < 2; ++np) {
                int row = wn * 32 + np * 16 + (lane & 15);
                uint32_t off = swz128((uint32_t)(row * 128 + chunk));
                ldsm4(br[0][np], B0 + off);
                ldsm4(br[1][np], B1 + off);
            }
#pragma unroll
            for (int mt = 0; mt < 4; ++mt) {
                int row = wm * 64 + mt * 16 + (lane & 15);
                uint32_t off = swz128((uint32_t)(row * 128 + chunk));
                uint32_t ah[4], al[4];
                ldsm4(ah, A0 + off);
                ldsm4(al, A1 + off);
#pragma unroll
                for (int nt = 0; nt < 4; ++nt) {
                    const int np = nt >> 1, hb = nt & 1;
                    const uint32_t bh0 = br[0][np][hb], bh1 = br[0][np][hb + 2];
                    const uint32_t bl0 = br[1][np][hb], bl1 = br[1][np][hb + 2];
                    mma16816(chi[mt][nt], ah, bh0, bh1);   // hh
                    mma16816(clo[mt][nt], ah, bl0, bl1);   // hl (x2^11)
                    mma16816(clo[mt][nt], al, bh0, bh1);   // lh (x2^11)
                }
            }
        }
    };

    load_tiles(0, 0);
    cp_commit();
    for (int kt = 0; kt < 32; ++kt) {
        if (kt + 1 < 32) {
            load_tiles((kt + 1) & 1, kt + 1);
            cp_commit();
            cp_wait<1>();
        } else {
            cp_wait<0>();
        }
        __syncthreads();
        compute(kt & 1);
        __syncthreads();
    }

    // epilogue: relu((chi + clo*2^-11) + b1) dot W2 -> partial
#pragma unroll
    for (int mt = 0; mt < 4; ++mt) {
#pragma unroll
        for (int h = 0; h < 2; ++h) {
            float p = 0.f;
#pragma unroll
            for (int nt = 0; nt < 4; ++nt)
#pragma unroll
                for (int e = 0; e < 2; ++e) {
                    int col = n0 + wn * 32 + nt * 8 + (lane & 3) * 2 + e;
                    float v = fmaf(clo[mt][nt][h * 2 + e], LO_INV,
                                   chi[mt][nt][h * 2 + e]) + b1[col];
                    v = fmaxf(v, 0.f);
                    p = fmaf(v, W2[col], p);
                }
            p += __shfl_xor_sync(0xffffffffu, p, 1);
            p += __shfl_xor_sync(0xffffffffu, p, 2);
            if ((lane & 3) == 0) {
                int row = wm * 64 + mt * 16 + (lane >> 2) + 8 * h;
                red[row][wn] = p;
            }
        }
    }
    __syncthreads();
    if (tid < 128) {
        float s = red[tid][0] + red[tid][1] + red[tid][2] + red[tid][3];
        g_partial[(size_t)(m0 + tid) * NCHUNK + blockIdx.x] = s;
    }
}

// ---------------- stage 2: logits -> sparsity, k -------------------
__global__ void sparsity_kernel(const float* __restrict__ b2,
                                float* __restrict__ out_sp)
{
    int b = blockIdx.x * 256 + threadIdx.x;
    if (b >= B_ROWS) return;
    float s = b2[0];
#pragma unroll
    for (int cc = 0; cc < NCHUNK; cc++) s += g_partial[(size_t)b * NCHUNK + cc];
    float sig = 1.f / (1.f + expf(-s));
    float sp  = 0.05f + 0.25f * sig;
    out_sp[b] = sp;
    int k = (int)rintf((float)D_DIM * (1.f - sp));   // round half-even
    g_k[b] = (k < 1) ? 1 : k;
}

// ---------------- stage 3: exact radix select (warp-scan) ----------
__global__ void __launch_bounds__(256) select_mask_kernel(
    const float* __restrict__ x,
    float* __restrict__ out_sparse, float* __restrict__ out_mask,
    float* __restrict__ out_act)
{
    __shared__ float        xs[D_DIM];
    __shared__ unsigned int hist[256];
    __shared__ unsigned int wsum[8];
    __shared__ float        fred[256];
    __shared__ unsigned int ired[256];
    __shared__ unsigned int s_prefix, s_kk;

    const int row  = blockIdx.x;
    const int tid  = threadIdx.x;
    const int lane = tid & 31;
    const int wid  = tid >> 5;
    const float* xr = x + (size_t)row * D_DIM;

#pragma unroll
    for (int p = 0; p < 2; p++) {
        int i4 = (tid + p * 256) * 4;
        *reinterpret_cast<float4*>(&xs[i4]) =
            *reinterpret_cast<const float4*>(&xr[i4]);
    }
    if (tid == 0) { s_prefix = 0u; s_kk = (unsigned int)g_k[row]; }
    hist[tid] = 0u;
    __syncthreads();

#pragma unroll
    for (int shift = 24; shift >= 0; shift -= 8) {
        const unsigned int prefix = s_prefix;
        const unsigned int kcur   = s_kk;
        const unsigned int himask = (shift == 24) ? 0u : (0xFFFFFFFFu << (shift + 8));
#pragma unroll
        for (int i = 0; i < 8; i++) {
            unsigned int key = __float_as_uint(fabsf(xs[tid + i * 256]));
            if ((key & himask) == prefix)
                atomicAdd(&hist[(key >> shift) & 255u], 1u);
        }
        __syncthreads();
        const unsigned int own = hist[tid];
        // warp inclusive scan
        unsigned int v = own;
#pragma unroll
        for (int off = 1; off < 32; off <<= 1) {
            unsigned int t = __shfl_up_sync(0xffffffffu, v, off);
            if (lane >= off) v += t;
        }
        if (lane == 31) wsum[wid] = v;
        __syncthreads();
        if (tid < 8) {
            unsigned int ws = wsum[tid];
#pragma unroll
            for (int off = 1; off < 8; off <<= 1) {
                unsigned int t = __shfl_up_sync(0xffu, ws, off, 8);
                if (tid >= off) ws += t;
            }
            wsum[tid] = ws;
        }
        __syncthreads();
        const unsigned int cum  = v + (wid ? wsum[wid - 1] : 0u);
        const unsigned int prev = cum - own;
        if (cum >= kcur && prev < kcur) {
            s_prefix = prefix | ((unsigned int)tid << shift);
            s_kk     = kcur - prev;
        }
        hist[tid] = 0u;          // re-zero for next pass
        __syncthreads();         // publishes s_prefix / s_kk
    }

    const float thr = __uint_as_float(s_prefix);

    unsigned int cnt = 0;
    float l1 = 0.f;
#pragma unroll
    for (int p = 0; p < 8; p++) {
        int i = tid + p * 256;
        float v = xs[i];
        float a = fabsf(v);
        bool  m = (a > thr);
        out_mask  [(size_t)row * D_DIM + i] = m ? 1.f : 0.f;
        out_sparse[(size_t)row * D_DIM + i] = m ? v : 0.f;
        if (m) { cnt++; l1 += a; }
    }
    ired[tid] = cnt;
    fred[tid] = l1;
    __syncthreads();
    for (int off = 128; off > 0; off >>= 1) {
        if (tid < off) {
            ired[tid] += ired[tid + off];
            fred[tid] += fred[tid + off];
        }
        __syncthreads();
    }
    if (tid == 0) {
        out_act[row] = (float)ired[0] / (float)D_DIM;
        g_l1row[row] = fred[0];
    }
}

// ---------------- stage 4: deterministic l1 mean -------------------
__global__ void l1_reduce(float* __restrict__ out_l1)
{
    __shared__ float sm[256];
    const int tid = threadIdx.x;
    float s = 0.f;
    for (int i = tid; i < B_ROWS; i += 256) s += g_l1row[i];
    sm[tid] = s;
    __syncthreads();
    for (int off = 128; off > 0; off >>= 1) {
        if (tid < off) sm[tid] += sm[tid + off];
        __syncthreads();
    }
    if (tid == 0) out_l1[0] = sm[0] / (float)B_ROWS;
}

// ---------------- launch ------------------------------------------
extern "C" void kernel_launch(void* const* d_in, const int* in_sizes, int n_in,
                              void* d_out, int out_size)
{
    const float* x  = (const float*)d_in[0];
    const float* W1 = (const float*)d_in[1];
    const float* b1 = (const float*)d_in[2];
    const float* W2 = (const float*)d_in[3];
    const float* b2 = (const float*)d_in[4];

    float* out        = (float*)d_out;
    float* out_sparse = out;                                   // [B, D]
    float* out_mask   = out + (size_t)B_ROWS * D_DIM;          // [B, D]
    float* out_sp     = out + 2 * (size_t)B_ROWS * D_DIM;      // [B, 1]
    float* out_act    = out_sp + B_ROWS;                       // [B]
    float* out_l1     = out_act + B_ROWS;                      // [1]

    cudaFuncSetAttribute(gemm_predictor,
                         cudaFuncAttributeMaxDynamicSharedMemorySize, SM_DYN);

    convert_x<<<(B_ROWS * (size_t)D_DIM) / (4 * 256), 256>>>(x);
    convert_w1<<<((size_t)D_DIM * H_DIM) / 256, 256>>>(W1);
    gemm_predictor<<<dim3(4, 128), 256, SM_DYN>>>(b1, W2);
    sparsity_kernel<<<B_ROWS / 256, 256>>>(b2, out_sp);
    select_mask_kernel<<<B_ROWS, 256>>>(x, out_sparse, out_mask, out_act);
    l1_reduce<<<1, 256>>>(out_l1);
}